// round 3
// baseline (speedup 1.0000x reference)
#include <cuda_runtime.h>
#include <cstdint>

#define NC 512
#define BATCH 128

// ---------------- device scratch (no allocation allowed) ----------------
__device__ int g_sym0[BATCH * 32 * 32];        // after discretize
__device__ int g_x1[BATCH * 14 * 14 * 6];      // after conv1+relu
__device__ int g_x2[BATCH * 5 * 5 * 16];       // after conv2+relu
__device__ int g_x3[BATCH * 120];              // after fc1+relu
__device__ int g_x4[BATCH * 84];               // after fc2+relu

// ---------------- Kernel A: discretize ----------------
__global__ void k_discretize(const float* __restrict__ x,
                             const float* __restrict__ cent) {
    __shared__ float sc[NC];
    for (int i = threadIdx.x; i < NC; i += blockDim.x) sc[i] = cent[i];
    __syncthreads();
    int idx = blockIdx.x * blockDim.x + threadIdx.x;
    if (idx >= BATCH * 32 * 32) return;
    float px = x[idx];
    float best = fabsf(px - sc[0]);
    int bi = 0;
#pragma unroll 8
    for (int i = 1; i < NC; i++) {
        float d = fabsf(px - sc[i]);
        if (d < best) { best = d; bi = i; }   // strict < keeps first-min (argmin tie rule)
    }
    g_sym0[idx] = bi;
}

// ---------------- Kernel B: conv1 (n=25) + bias + relu ----------------
// One thread per (b, oh, ow, co). Sorted u16 array of 25 in smem (strided).
#define C1_ROWS (BATCH * 14 * 14 * 6)
#define C1_T 256
__global__ __launch_bounds__(C1_T)
void k_conv1(const int* __restrict__ conv_lut, const int* __restrict__ add_lut,
             const int* __restrict__ c1f, const int* __restrict__ bias,
             const int* __restrict__ relu) {
    __shared__ unsigned short arr[25 * C1_T];
    __shared__ int sw[25 * 6];
    for (int i = threadIdx.x; i < 150; i += blockDim.x) sw[i] = c1f[i];
    __syncthreads();
    int row = blockIdx.x * C1_T + threadIdx.x;
    if (row >= C1_ROWS) return;
    int tid = threadIdx.x;
    int co = row % 6;
    int t = row / 6;
    int ow = t % 14; t /= 14;
    int oh = t % 14;
    int b = t / 14;

#define A1(j) arr[(j) * C1_T + tid]
    const int* base = g_sym0 + b * 1024 + (oh * 2) * 32 + (ow * 2);
    int i = 0;
    for (int di = 0; di < 5; di++)
        for (int dj = 0; dj < 5; dj++) {
            int win = base[di * 32 + dj];
            int g = conv_lut[win * NC + sw[i * 6 + co]];
            A1(i) = (unsigned short)g;
            i++;
        }
    // insertion sort (25)
    for (int ii = 1; ii < 25; ii++) {
        unsigned short key = A1(ii);
        int j = ii - 1;
        while (j >= 0 && A1(j) > key) { A1(j + 1) = A1(j); j--; }
        A1(j + 1) = key;
    }
    // conv_reduce (exact replica of reference semantics)
    int tmp = A1(0);
    for (int j = 1; j < 25; j++) {
        int xv = A1(j);
        int t2 = add_lut[xv * NC + tmp];
        if (j < 23) {                      // j < n-2
            int nxt = A1(j + 1);
            if (t2 > nxt) {
                // remove a[j+1], insert t2 into sorted suffix
                int p = j + 1;
                while (p + 1 < 25) {
                    unsigned short nx = A1(p + 1);
                    if ((int)nx < t2) { A1(p) = nx; p++; }
                    else break;
                }
                A1(p) = (unsigned short)t2;
                tmp = nxt;
            } else tmp = t2;
        } else tmp = t2;
    }
    g_x1[row] = relu[bias[tmp * 6 + co]];
#undef A1
}

// ---------------- Kernel C: conv2 (n=150) via hist+bitmap PQ ----------------
#define C2_ROWS (BATCH * 5 * 5 * 16)
#define C2_T 384
extern __shared__ unsigned int dyn_smem[];
__global__ __launch_bounds__(C2_T, 1)
void k_conv2(const int* __restrict__ conv_lut, const int* __restrict__ add_lut,
             const int* __restrict__ c2f, const int* __restrict__ bias,
             const int* __restrict__ relu) {
    unsigned int* bm = dyn_smem;              // 16*T words (512-bit bitmap / thread)
    unsigned int* hw = dyn_smem + 16 * C2_T;  // 128*T words (512 u8 counters / thread)
    int tid = threadIdx.x;
    int row = blockIdx.x * C2_T + tid;
    if (row >= C2_ROWS) return;

    for (int k = 0; k < 16; k++) bm[k * C2_T + tid] = 0;
    for (int k = 0; k < 128; k++) hw[k * C2_T + tid] = 0;

    int co = row % 16;
    int t = row / 16;
    int ow = t % 5; t /= 5;
    int oh = t % 5;
    int b = t / 5;

    const int* base = g_x1 + ((b * 14 + oh * 2) * 14 + ow * 2) * 6;
    int i = 0;
    for (int di = 0; di < 5; di++)
        for (int dj = 0; dj < 5; dj++) {
            const int* p = base + (di * 14 + dj) * 6;
#pragma unroll
            for (int c = 0; c < 6; c++) {
                int win = p[c];
                int g = conv_lut[win * NC + c2f[i * 16 + co]];
                unsigned char* bp =
                    (unsigned char*)(hw + ((g >> 2) * C2_T + tid)) + (g & 3);
                *bp = (unsigned char)(*bp + 1);
                bm[(g >> 5) * C2_T + tid] |= 1u << (g & 31);
                i++;
            }
        }

    int wi = 0;
    auto peek = [&](unsigned int& w) -> int {
        w = bm[wi * C2_T + tid];
        while (w == 0 && wi < 15) { wi++; w = bm[wi * C2_T + tid]; }
        return wi * 32 + (__ffs((int)w) - 1);
    };
    auto dec = [&](int v, unsigned int w) {
        unsigned char* bp =
            (unsigned char*)(hw + ((v >> 2) * C2_T + tid)) + (v & 3);
        unsigned char c = *bp; c--; *bp = c;
        if (c == 0) bm[(v >> 5) * C2_T + tid] = w & ~(1u << (v & 31));
    };

    unsigned int w;
    int v = peek(w); dec(v, w);
    int tmp = v;
    const int n = 150;
    for (int j = 1; j < n; j++) {
        v = peek(w); dec(v, w);
        int t2 = add_lut[v * NC + tmp];
        if (j < n - 2) {
            unsigned int w2;
            int nxt = peek(w2);
            if (t2 > nxt) {
                dec(nxt, w2);
                unsigned char* bp =
                    (unsigned char*)(hw + ((t2 >> 2) * C2_T + tid)) + (t2 & 3);
                *bp = (unsigned char)(*bp + 1);
                bm[(t2 >> 5) * C2_T + tid] |= 1u << (t2 & 31);
                tmp = nxt;
            } else tmp = t2;
        } else tmp = t2;
    }
    g_x2[row] = relu[bias[tmp * 16 + co]];
}

// ---------------- Kernel D: fc1 (n=400, pure sorted fold) ----------------
#define FC1_T 120
__global__ __launch_bounds__(FC1_T, 1)
void k_fc1(const int* __restrict__ fc_lut, const int* __restrict__ add_lut,
           const int* __restrict__ f1f, const int* __restrict__ bias,
           const int* __restrict__ relu) {
    unsigned int* bm = dyn_smem;                    // 16*T
    unsigned int* hw = dyn_smem + 16 * FC1_T;       // 256*T words (512 u16 / thread)
    int* xr = (int*)(dyn_smem + (16 + 256) * FC1_T);  // 400 ints staged x row
    int tid = threadIdx.x;
    int b = blockIdx.x;

    for (int i = tid; i < 400; i += FC1_T) {
        int c = i / 25;
        int r = i % 25;
        int oh = r / 5, ow = r % 5;
        xr[i] = g_x2[((b * 5 + oh) * 5 + ow) * 16 + c];  // transpose(0,3,1,2) flatten
    }
    for (int k = 0; k < 16; k++) bm[k * FC1_T + tid] = 0;
    for (int k = 0; k < 256; k++) hw[k * FC1_T + tid] = 0;
    __syncthreads();

    int m = tid;
    const int* wrow = f1f + m * 400;
    for (int i = 0; i < 400; i++) {
        int g = fc_lut[xr[i] * NC + wrow[i]];
        unsigned short* hp =
            (unsigned short*)(hw + ((g >> 1) * FC1_T + tid)) + (g & 1);
        *hp = (unsigned short)(*hp + 1);
        bm[(g >> 5) * FC1_T + tid] |= 1u << (g & 31);
    }
    int tmp = 0;
    bool first = true;
    for (int wi = 0; wi < 16; wi++) {
        unsigned int w = bm[wi * FC1_T + tid];
        while (w) {
            int bit = __ffs((int)w) - 1;
            w &= w - 1;
            int v = wi * 32 + bit;
            unsigned short* hp =
                (unsigned short*)(hw + ((v >> 1) * FC1_T + tid)) + (v & 1);
            int c = *hp;
            if (first) { tmp = v; c--; first = false; }
            for (int k = 0; k < c; k++) tmp = add_lut[v * NC + tmp];
        }
    }
    g_x3[b * 120 + m] = relu[bias[tmp * 120 + m]];
}

// ---------------- Kernel E: fc2 (n=120, pure sorted fold, u8 hist) ----------------
#define FC2_T 84
__global__ __launch_bounds__(FC2_T, 1)
void k_fc2(const int* __restrict__ fc_lut, const int* __restrict__ add_lut,
           const int* __restrict__ f2f, const int* __restrict__ bias,
           const int* __restrict__ relu) {
    unsigned int* bm = dyn_smem;                    // 16*T
    unsigned int* hw = dyn_smem + 16 * FC2_T;       // 128*T words (512 u8 / thread)
    int* xr = (int*)(dyn_smem + (16 + 128) * FC2_T);  // 120 ints
    int tid = threadIdx.x;
    int b = blockIdx.x;

    for (int i = tid; i < 120; i += FC2_T) xr[i] = g_x3[b * 120 + i];
    for (int k = 0; k < 16; k++) bm[k * FC2_T + tid] = 0;
    for (int k = 0; k < 128; k++) hw[k * FC2_T + tid] = 0;
    __syncthreads();

    int m = tid;
    const int* wrow = f2f + m * 120;
    for (int i = 0; i < 120; i++) {
        int g = fc_lut[xr[i] * NC + wrow[i]];
        unsigned char* bp =
            (unsigned char*)(hw + ((g >> 2) * FC2_T + tid)) + (g & 3);
        *bp = (unsigned char)(*bp + 1);
        bm[(g >> 5) * FC2_T + tid] |= 1u << (g & 31);
    }
    int tmp = 0;
    bool first = true;
    for (int wi = 0; wi < 16; wi++) {
        unsigned int w = bm[wi * FC2_T + tid];
        while (w) {
            int bit = __ffs((int)w) - 1;
            w &= w - 1;
            int v = wi * 32 + bit;
            unsigned char* bp =
                (unsigned char*)(hw + ((v >> 2) * FC2_T + tid)) + (v & 3);
            int c = *bp;
            if (first) { tmp = v; c--; first = false; }
            for (int k = 0; k < c; k++) tmp = add_lut[v * NC + tmp];
        }
    }
    g_x4[b * 84 + m] = relu[bias[tmp * 84 + m]];
}

// ---------------- Kernel F: head (feats @ W^T + b, softmax) ----------------
__global__ void k_head(const float* __restrict__ cent,
                       const float* __restrict__ w,
                       const float* __restrict__ bvec,
                       float* __restrict__ out) {
    int b = blockIdx.x * blockDim.x + threadIdx.x;
    if (b >= BATCH) return;
    float f[84];
#pragma unroll
    for (int i = 0; i < 84; i++) f[i] = cent[g_x4[b * 84 + i]];
    float lg[10];
    float mx = -1e30f;
#pragma unroll
    for (int k = 0; k < 10; k++) {
        float s = bvec[k];
#pragma unroll
        for (int i = 0; i < 84; i++) s += f[i] * w[k * 84 + i];
        lg[k] = s;
        mx = fmaxf(mx, s);
    }
    float sum = 0.f;
#pragma unroll
    for (int k = 0; k < 10; k++) { lg[k] = __expf(lg[k] - mx); sum += lg[k]; }
    float inv = 1.f / sum;
#pragma unroll
    for (int k = 0; k < 10; k++) out[b * 10 + k] = lg[k] * inv;
}

// ---------------- launch ----------------
extern "C" void kernel_launch(void* const* d_in, const int* in_sizes, int n_in,
                              void* d_out, int out_size) {
    const float* x_bat   = (const float*)d_in[0];
    const float* cent    = (const float*)d_in[1];
    const int* conv_lut  = (const int*)d_in[2];
    const int* fc_lut    = (const int*)d_in[3];
    const int* add_lut   = (const int*)d_in[4];
    const int* relu_lut  = (const int*)d_in[5];
    const int* c1_bias   = (const int*)d_in[6];
    const int* c2_bias   = (const int*)d_in[7];
    const int* f1_bias   = (const int*)d_in[8];
    const int* f2_bias   = (const int*)d_in[9];
    const int* c1f       = (const int*)d_in[10];
    const int* c2f       = (const int*)d_in[11];
    const int* f1f       = (const int*)d_in[12];
    const int* f2f       = (const int*)d_in[13];
    const float* fc3_w   = (const float*)d_in[14];
    const float* fc3_b   = (const float*)d_in[15];
    float* out           = (float*)d_out;

    size_t c2_smem  = (size_t)(16 + 128) * C2_T * 4;                 // 221184
    size_t fc1_smem = (size_t)(16 + 256) * FC1_T * 4 + 400 * 4;      // 132160
    size_t fc2_smem = (size_t)(16 + 128) * FC2_T * 4 + 120 * 4;      //  48864
    cudaFuncSetAttribute(k_conv2, cudaFuncAttributeMaxDynamicSharedMemorySize,
                         (int)c2_smem);
    cudaFuncSetAttribute(k_fc1, cudaFuncAttributeMaxDynamicSharedMemorySize,
                         (int)fc1_smem);
    cudaFuncSetAttribute(k_fc2, cudaFuncAttributeMaxDynamicSharedMemorySize,
                         (int)fc2_smem);

    k_discretize<<<(BATCH * 32 * 32 + 255) / 256, 256>>>(x_bat, cent);
    k_conv1<<<(C1_ROWS + C1_T - 1) / C1_T, C1_T>>>(conv_lut, add_lut, c1f,
                                                   c1_bias, relu_lut);
    k_conv2<<<(C2_ROWS + C2_T - 1) / C2_T, C2_T, c2_smem>>>(conv_lut, add_lut,
                                                            c2f, c2_bias,
                                                            relu_lut);
    k_fc1<<<BATCH, FC1_T, fc1_smem>>>(fc_lut, add_lut, f1f, f1_bias, relu_lut);
    k_fc2<<<BATCH, FC2_T, fc2_smem>>>(fc_lut, add_lut, f2f, f2_bias, relu_lut);
    k_head<<<1, BATCH>>>(cent, fc3_w, fc3_b, out);
}

// round 5
// speedup vs baseline: 1.4284x; 1.4284x over previous
#include <cuda_runtime.h>
#include <cstdint>

#define NC 512
#define BATCH 128

// ---------------- device scratch (no allocation allowed) ----------------
__device__ int g_sym0[BATCH * 32 * 32];        // after discretize
__device__ int g_x1[BATCH * 14 * 14 * 6];      // after conv1+relu
__device__ int g_x2[BATCH * 5 * 5 * 16];       // after conv2+relu
__device__ int g_x3[BATCH * 120];              // after fc1+relu
__device__ int g_x4[BATCH * 84];               // after fc2+relu

// ---------------- Kernel A: discretize ----------------
__global__ void k_discretize(const float* __restrict__ x,
                             const float* __restrict__ cent) {
    __shared__ float sc[NC];
    for (int i = threadIdx.x; i < NC; i += blockDim.x) sc[i] = cent[i];
    __syncthreads();
    int idx = blockIdx.x * blockDim.x + threadIdx.x;
    if (idx >= BATCH * 32 * 32) return;
    float px = x[idx];
    float best = fabsf(px - sc[0]);
    int bi = 0;
#pragma unroll 8
    for (int i = 1; i < NC; i++) {
        float d = fabsf(px - sc[i]);
        if (d < best) { best = d; bi = i; }   // strict < keeps first-min (argmin tie rule)
    }
    g_sym0[idx] = bi;
}

// ---------------- Kernel B: conv1 (n=25) + bias + relu ----------------
#define C1_ROWS (BATCH * 14 * 14 * 6)
#define C1_T 256
__global__ __launch_bounds__(C1_T)
void k_conv1(const int* __restrict__ conv_lut, const int* __restrict__ add_lut,
             const int* __restrict__ c1f, const int* __restrict__ bias,
             const int* __restrict__ relu) {
    __shared__ unsigned short arr[25 * C1_T];
    __shared__ int sw[25 * 6];
    for (int i = threadIdx.x; i < 150; i += blockDim.x) sw[i] = c1f[i];
    __syncthreads();
    int row = blockIdx.x * C1_T + threadIdx.x;
    if (row >= C1_ROWS) return;
    int tid = threadIdx.x;
    int co = row % 6;
    int t = row / 6;
    int ow = t % 14; t /= 14;
    int oh = t % 14;
    int b = t / 14;

#define A1(j) arr[(j) * C1_T + tid]
    const int* base = g_sym0 + b * 1024 + (oh * 2) * 32 + (ow * 2);
    int i = 0;
    for (int di = 0; di < 5; di++)
        for (int dj = 0; dj < 5; dj++) {
            int win = base[di * 32 + dj];
            int g = conv_lut[win * NC + sw[i * 6 + co]];
            A1(i) = (unsigned short)g;
            i++;
        }
    // insertion sort (25)
    for (int ii = 1; ii < 25; ii++) {
        unsigned short key = A1(ii);
        int j = ii - 1;
        while (j >= 0 && A1(j) > key) { A1(j + 1) = A1(j); j--; }
        A1(j + 1) = key;
    }
    // conv_reduce (exact replica of reference semantics)
    int tmp = A1(0);
    for (int j = 1; j < 25; j++) {
        int xv = A1(j);
        int t2 = add_lut[xv * NC + tmp];
        if (j < 23) {                      // j < n-2
            int nxt = A1(j + 1);
            if (t2 > nxt) {
                int p = j + 1;
                while (p + 1 < 25) {
                    unsigned short nx = A1(p + 1);
                    if ((int)nx < t2) { A1(p) = nx; p++; }
                    else break;
                }
                A1(p) = (unsigned short)t2;
                tmp = nxt;
            } else tmp = t2;
        } else tmp = t2;
    }
    g_x1[row] = relu[bias[tmp * 6 + co]];
#undef A1
}

// ---------------- Kernel C: conv2 (n=150) via hist+bitmap PQ ----------------
#define C2_ROWS (BATCH * 5 * 5 * 16)
#define C2_T 384
extern __shared__ unsigned int dyn_smem[];
__global__ __launch_bounds__(C2_T, 1)
void k_conv2(const int* __restrict__ conv_lut, const int* __restrict__ add_lut,
             const int* __restrict__ c2f, const int* __restrict__ bias,
             const int* __restrict__ relu) {
    unsigned int* bm = dyn_smem;              // 16*T words (512-bit bitmap / thread)
    unsigned int* hw = dyn_smem + 16 * C2_T;  // 128*T words (512 u8 counters / thread)
    int tid = threadIdx.x;
    int row = blockIdx.x * C2_T + tid;
    if (row >= C2_ROWS) return;

    for (int k = 0; k < 16; k++) bm[k * C2_T + tid] = 0;
    for (int k = 0; k < 128; k++) hw[k * C2_T + tid] = 0;

    int co = row % 16;
    int t = row / 16;
    int ow = t % 5; t /= 5;
    int oh = t % 5;
    int b = t / 5;

    const int* base = g_x1 + ((b * 14 + oh * 2) * 14 + ow * 2) * 6;
    int i = 0;
    for (int di = 0; di < 5; di++)
        for (int dj = 0; dj < 5; dj++) {
            const int* p = base + (di * 14 + dj) * 6;
#pragma unroll
            for (int c = 0; c < 6; c++) {
                int win = p[c];
                int g = conv_lut[win * NC + c2f[i * 16 + co]];
                unsigned char* bp =
                    (unsigned char*)(hw + ((g >> 2) * C2_T + tid)) + (g & 3);
                *bp = (unsigned char)(*bp + 1);
                bm[(g >> 5) * C2_T + tid] |= 1u << (g & 31);
                i++;
            }
        }

    int wi = 0;
    auto peek = [&](unsigned int& w) -> int {
        w = bm[wi * C2_T + tid];
        while (w == 0 && wi < 15) { wi++; w = bm[wi * C2_T + tid]; }
        return wi * 32 + (__ffs((int)w) - 1);
    };
    auto dec = [&](int v, unsigned int w) {
        unsigned char* bp =
            (unsigned char*)(hw + ((v >> 2) * C2_T + tid)) + (v & 3);
        unsigned char c = *bp; c--; *bp = c;
        if (c == 0) bm[(v >> 5) * C2_T + tid] = w & ~(1u << (v & 31));
    };

    unsigned int w;
    int v = peek(w); dec(v, w);
    int tmp = v;
    const int n = 150;
    for (int j = 1; j < n; j++) {
        v = peek(w); dec(v, w);
        int t2 = add_lut[v * NC + tmp];
        if (j < n - 2) {
            unsigned int w2;
            int nxt = peek(w2);
            if (t2 > nxt) {
                dec(nxt, w2);
                unsigned char* bp =
                    (unsigned char*)(hw + ((t2 >> 2) * C2_T + tid)) + (t2 & 3);
                *bp = (unsigned char)(*bp + 1);
                bm[(t2 >> 5) * C2_T + tid] |= 1u << (t2 & 31);
                tmp = nxt;
            } else tmp = t2;
        } else tmp = t2;
    }
    g_x2[row] = relu[bias[tmp * 16 + co]];
}

// ---------------- Kernel D: fc1 (n=400) hist -> counting-sort -> UNIFORM fold ----------------
#define FC1_T 120
#define FC1_N 400
__global__ __launch_bounds__(FC1_T, 1)
void k_fc1(const int* __restrict__ fc_lut, const int* __restrict__ add_lut,
           const int* __restrict__ f1f, const int* __restrict__ bias,
           const int* __restrict__ relu) {
    // layout: xr[400] ints | hist u16[512][T] | arr u16[400][T]
    int* xr = (int*)dyn_smem;
    unsigned short* hist = (unsigned short*)(xr + FC1_N);
    unsigned short* arr = hist + NC * FC1_T;
    int tid = threadIdx.x;
    int b = blockIdx.x;

    for (int i = tid; i < FC1_N; i += FC1_T) {
        int c = i / 25;
        int r = i % 25;
        int oh = r / 5, ow = r % 5;
        xr[i] = g_x2[((b * 5 + oh) * 5 + ow) * 16 + c];  // transpose(0,3,1,2) flatten
    }
    // cooperative zero of hist (u32 writes)
    {
        unsigned int* hz = (unsigned int*)hist;
        for (int i = tid; i < NC * FC1_T / 2; i += FC1_T) hz[i] = 0;
    }
    __syncthreads();

    int m = tid;
    const int* wrow = f1f + m * FC1_N;
    // chunked build: batch 8 independent gathers before touching smem hist
    for (int i0 = 0; i0 < FC1_N; i0 += 8) {
        int xv[8], wv[8], g[8];
#pragma unroll
        for (int k = 0; k < 8; k++) { xv[k] = xr[i0 + k]; wv[k] = wrow[i0 + k]; }
#pragma unroll
        for (int k = 0; k < 8; k++) g[k] = fc_lut[(xv[k] << 9) + wv[k]];
#pragma unroll
        for (int k = 0; k < 8; k++) hist[g[k] * FC1_T + tid]++;
    }
    // counting-sort expansion into per-thread sorted array
    {
        int p = 0;
        for (int v = 0; v < NC; v++) {
            int c = hist[v * FC1_T + tid];
            while (c--) { arr[p * FC1_T + tid] = (unsigned short)v; p++; }
        }
    }
    // uniform fold: all lanes advance in lockstep, 1 chain LDG per iter
    int tmp = arr[0 * FC1_T + tid];
    for (int i = 1; i < FC1_N; i++) {
        int v = arr[i * FC1_T + tid];
        tmp = add_lut[(v << 9) + tmp];
    }
    g_x3[b * 120 + m] = relu[bias[tmp * 120 + m]];
}

// ---------------- Kernel E: fc2 (n=120) hist -> counting-sort -> UNIFORM fold ----------------
#define FC2_T 84
#define FC2_N 120
__global__ __launch_bounds__(FC2_T, 1)
void k_fc2(const int* __restrict__ fc_lut, const int* __restrict__ add_lut,
           const int* __restrict__ f2f, const int* __restrict__ bias,
           const int* __restrict__ relu) {
    // layout: xr[120] ints | hist u8[512][T] | arr u16[120][T]
    int* xr = (int*)dyn_smem;
    unsigned char* hist = (unsigned char*)(xr + FC2_N);
    unsigned short* arr = (unsigned short*)(hist + NC * FC2_T);
    int tid = threadIdx.x;
    int b = blockIdx.x;

    for (int i = tid; i < FC2_N; i += FC2_T) xr[i] = g_x3[b * 120 + i];
    {
        unsigned int* hz = (unsigned int*)hist;
        for (int i = tid; i < NC * FC2_T / 4; i += FC2_T) hz[i] = 0;
    }
    __syncthreads();

    int m = tid;
    const int* wrow = f2f + m * FC2_N;
    for (int i0 = 0; i0 < FC2_N; i0 += 8) {
        int xv[8], wv[8], g[8];
#pragma unroll
        for (int k = 0; k < 8; k++) { xv[k] = xr[i0 + k]; wv[k] = wrow[i0 + k]; }
#pragma unroll
        for (int k = 0; k < 8; k++) g[k] = fc_lut[(xv[k] << 9) + wv[k]];
#pragma unroll
        for (int k = 0; k < 8; k++) hist[g[k] * FC2_T + tid]++;
    }
    {
        int p = 0;
        for (int v = 0; v < NC; v++) {
            int c = hist[v * FC2_T + tid];
            while (c--) { arr[p * FC2_T + tid] = (unsigned short)v; p++; }
        }
    }
    int tmp = arr[0 * FC2_T + tid];
    for (int i = 1; i < FC2_N; i++) {
        int v = arr[i * FC2_T + tid];
        tmp = add_lut[(v << 9) + tmp];
    }
    g_x4[b * 84 + m] = relu[bias[tmp * 84 + m]];
}

// ---------------- Kernel F: head (feats @ W^T + b, softmax) ----------------
__global__ void k_head(const float* __restrict__ cent,
                       const float* __restrict__ w,
                       const float* __restrict__ bvec,
                       float* __restrict__ out) {
    int b = blockIdx.x * blockDim.x + threadIdx.x;
    if (b >= BATCH) return;
    float f[84];
#pragma unroll
    for (int i = 0; i < 84; i++) f[i] = cent[g_x4[b * 84 + i]];
    float lg[10];
    float mx = -1e30f;
#pragma unroll
    for (int k = 0; k < 10; k++) {
        float s = bvec[k];
#pragma unroll
        for (int i = 0; i < 84; i++) s += f[i] * w[k * 84 + i];
        lg[k] = s;
        mx = fmaxf(mx, s);
    }
    float sum = 0.f;
#pragma unroll
    for (int k = 0; k < 10; k++) { lg[k] = __expf(lg[k] - mx); sum += lg[k]; }
    float inv = 1.f / sum;
#pragma unroll
    for (int k = 0; k < 10; k++) out[b * 10 + k] = lg[k] * inv;
}

// ---------------- launch ----------------
extern "C" void kernel_launch(void* const* d_in, const int* in_sizes, int n_in,
                              void* d_out, int out_size) {
    const float* x_bat   = (const float*)d_in[0];
    const float* cent    = (const float*)d_in[1];
    const int* conv_lut  = (const int*)d_in[2];
    const int* fc_lut    = (const int*)d_in[3];
    const int* add_lut   = (const int*)d_in[4];
    const int* relu_lut  = (const int*)d_in[5];
    const int* c1_bias   = (const int*)d_in[6];
    const int* c2_bias   = (const int*)d_in[7];
    const int* f1_bias   = (const int*)d_in[8];
    const int* f2_bias   = (const int*)d_in[9];
    const int* c1f       = (const int*)d_in[10];
    const int* c2f       = (const int*)d_in[11];
    const int* f1f       = (const int*)d_in[12];
    const int* f2f       = (const int*)d_in[13];
    const float* fc3_w   = (const float*)d_in[14];
    const float* fc3_b   = (const float*)d_in[15];
    float* out           = (float*)d_out;

    size_t c2_smem  = (size_t)(16 + 128) * C2_T * 4;                         // 221184
    size_t fc1_smem = (size_t)FC1_N * 4 + (size_t)NC * FC1_T * 2
                    + (size_t)FC1_N * FC1_T * 2;                             // 220480
    size_t fc2_smem = (size_t)FC2_N * 4 + (size_t)NC * FC2_T
                    + (size_t)FC2_N * FC2_T * 2;                             //  63648
    cudaFuncSetAttribute(k_conv2, cudaFuncAttributeMaxDynamicSharedMemorySize,
                         (int)c2_smem);
    cudaFuncSetAttribute(k_fc1, cudaFuncAttributeMaxDynamicSharedMemorySize,
                         (int)fc1_smem);
    cudaFuncSetAttribute(k_fc2, cudaFuncAttributeMaxDynamicSharedMemorySize,
                         (int)fc2_smem);

    k_discretize<<<(BATCH * 32 * 32 + 255) / 256, 256>>>(x_bat, cent);
    k_conv1<<<(C1_ROWS + C1_T - 1) / C1_T, C1_T>>>(conv_lut, add_lut, c1f,
                                                   c1_bias, relu_lut);
    k_conv2<<<(C2_ROWS + C2_T - 1) / C2_T, C2_T, c2_smem>>>(conv_lut, add_lut,
                                                            c2f, c2_bias,
                                                            relu_lut);
    k_fc1<<<BATCH, FC1_T, fc1_smem>>>(fc_lut, add_lut, f1f, f1_bias, relu_lut);
    k_fc2<<<BATCH, FC2_T, fc2_smem>>>(fc_lut, add_lut, f2f, f2_bias, relu_lut);
    k_head<<<1, BATCH>>>(cent, fc3_w, fc3_b, out);
}